// round 1
// baseline (speedup 1.0000x reference)
#include <cuda_runtime.h>
#include <cuda_bf16.h>
#include <math.h>

// Problem constants
#define B_   16
#define CIN  64
#define COUT 64
#define H_   128
#define W_   128
#define KK   5
#define HW   (H_*W_)          // 16384
#define NPIX (B_*COUT*HW)     // 16,777,216

// ---------------- device scratch (static, no allocation) ----------------
__device__ __align__(16) float g_wt[25 * CIN * COUT];   // [khw][ci][o], normalized |w|
__device__ float g_dog[25];                             // normalized DoG kernel
__device__ __align__(16) float g_ybuf[NPIX];            // cosine-sim intermediate

// ---------------- helpers ----------------
__device__ __forceinline__ int refl(int i) {
    // jnp.pad mode='reflect' (no edge repeat), valid for pad<=2, size 128
    if (i < 0) return -i;
    if (i > 127) return 254 - i;
    return i;
}

// ---------------- kernel 1: weight normalization + DoG table ----------------
__global__ void prep_kernel(const float* __restrict__ w) {
    int t = blockIdx.x * blockDim.x + threadIdx.x;
    if (t < 1600) {
        int o = t / 25, khw = t % 25;
        float s = 0.f;
        #pragma unroll 8
        for (int ci = 0; ci < CIN; ci++) {
            float v = w[o * 1600 + ci * 25 + khw];
            s += v * v;
        }
        float inv = 1.f / fmaxf(sqrtf(s), 1e-12f);
        #pragma unroll 8
        for (int ci = 0; ci < CIN; ci++) {
            float v = fabsf(w[o * 1600 + ci * 25 + khw]);
            g_wt[khw * (CIN * COUT) + ci * COUT + o] = v * inv;
        }
    }
    if (t < 25) {
        int u = t / 5 - 2, v = t % 5 - 2;
        float d2 = (float)(u * u + v * v);
        const float two_pi = 6.2831853071795864769f;
        const float ae = 1.f / (two_pi * 1.44f);   // sigma_e = 1.2
        const float ai = 1.f / (two_pi * 1.96f);   // sigma_i = 1.4
        float val = ae * expf(-d2 / (2.f * 1.44f)) - ai * expf(-d2 / (2.f * 1.96f));
        float ctr = ae - ai;
        g_dog[t] = val / ctr;
    }
}

// ---------------- kernel 2: main conv + cosine normalization ----------------
// Grid: (128 y-rows, 16 batches). Block: 256 threads.
// Each block computes y_cos[b, 0:64, y, 0:128].
// smem layout (dynamic): Ws[5][64][64] (20480 f) | Xs[64][132] (8448 f) | Ssum[132]
#define SMEM_FLOATS (20480 + 8448 + 132)

__global__ __launch_bounds__(256, 1)
void main_conv_kernel(const float* __restrict__ x) {
    extern __shared__ float sm[];
    float* Ws   = sm;                 // [kw][ci][o] for current kh
    float* Xs   = sm + 20480;         // [ci][132] padded row
    float* Ssum = Xs + 8448;          // per-column sum of x^2 over ci,kh

    const int tid = threadIdx.x;
    const int y   = blockIdx.x;
    const int b   = blockIdx.y;
    const int cg  = tid >> 5;         // cout group 0..7 (8 couts each)
    const int pg  = tid & 31;         // pixel group 0..31 (4 px each)
    const int p0  = pg * 4;

    float acc[8][4];
    #pragma unroll
    for (int c = 0; c < 8; c++)
        #pragma unroll
        for (int i = 0; i < 4; i++) acc[c][i] = 0.f;

    if (tid < 132) Ssum[tid] = 0.f;

    const float* xb = x + (size_t)b * CIN * HW;

    for (int kh = 0; kh < 5; kh++) {
        // ---- load weights: 5 matrices [kw][ci][o] contiguous in g_wt ----
        {
            const float4* src = (const float4*)(g_wt + kh * 5 * (CIN * COUT));
            float4* dst = (float4*)Ws;
            #pragma unroll
            for (int i = 0; i < 20; i++) dst[tid + i * 256] = src[tid + i * 256];
        }
        // ---- load padded x row for all 64 channels ----
        {
            int ry = refl(y + kh - 2);
            for (int idx = tid; idx < CIN * 132; idx += 256) {
                int ci = idx / 132;
                int c  = idx - ci * 132;
                int rc = refl(c - 2);
                Xs[idx] = xb[ci * HW + ry * W_ + rc];
            }
        }
        __syncthreads();

        // ---- per-column sum of squares over ci (threads < 132) ----
        if (tid < 132) {
            float s = 0.f;
            #pragma unroll 8
            for (int ci = 0; ci < CIN; ci++) {
                float v = Xs[ci * 132 + tid];
                s += v * v;
            }
            Ssum[tid] += s;
        }

        // ---- GEMM: acc[co][i] += W[kw][ci][co] * X[ci][p0+kw+i] ----
        for (int ci = 0; ci < CIN; ci++) {
            const float* xp = &Xs[ci * 132 + p0];
            float4 xa = *(const float4*)xp;
            float4 xc = *(const float4*)(xp + 4);
            float xv[8] = {xa.x, xa.y, xa.z, xa.w, xc.x, xc.y, xc.z, xc.w};
            #pragma unroll
            for (int kw = 0; kw < 5; kw++) {
                const float* wp = &Ws[(kw * CIN + ci) * COUT + cg * 8];
                float4 w0 = *(const float4*)wp;
                float4 w1 = *(const float4*)(wp + 4);
                float wv[8] = {w0.x, w0.y, w0.z, w0.w, w1.x, w1.y, w1.z, w1.w};
                #pragma unroll
                for (int co = 0; co < 8; co++)
                    #pragma unroll
                    for (int i = 0; i < 4; i++)
                        acc[co][i] = fmaf(wv[co], xv[kw + i], acc[co][i]);
            }
        }
        __syncthreads();   // before overwriting Xs/Ws next kh; also publishes Ssum
    }

    // ---- epilogue: divide by patch norm, write y_cos ----
    float inv[4];
    #pragma unroll
    for (int i = 0; i < 4; i++) {
        float s = Ssum[p0 + i] + Ssum[p0 + i + 1] + Ssum[p0 + i + 2]
                + Ssum[p0 + i + 3] + Ssum[p0 + i + 4];
        inv[i] = rsqrtf(s + 1e-8f);
    }
    #pragma unroll
    for (int co = 0; co < 8; co++) {
        float4 v = make_float4(acc[co][0] * inv[0], acc[co][1] * inv[1],
                               acc[co][2] * inv[2], acc[co][3] * inv[3]);
        int oc = cg * 8 + co;
        *(float4*)&g_ybuf[((size_t)(b * COUT + oc) * H_ + y) * W_ + p0] = v;
    }
}

// ---------------- kernel 3: depthwise 5x5 DoG (zero padding) ----------------
// Grid: (1024 images, 8 row-tiles). Block: 512 threads, each does 4 px of a 16x128 tile.
__global__ __launch_bounds__(512)
void dog_kernel(float* __restrict__ out) {
    __shared__ float Ts[20 * 132];
    __shared__ float sd[25];

    const int tid = threadIdx.x;
    const int bc  = blockIdx.x;           // b*64 + co
    const int y0  = blockIdx.y * 16;

    if (tid < 25) sd[tid] = g_dog[tid];

    const float* src = g_ybuf + (size_t)bc * HW;
    for (int idx = tid; idx < 20 * 132; idx += 512) {
        int r = idx / 132;
        int c = idx - r * 132;
        int gy = y0 + r - 2;
        int gx = c - 2;
        float v = 0.f;
        if (gy >= 0 && gy < H_ && gx >= 0 && gx < W_) v = src[gy * W_ + gx];
        Ts[idx] = v;
    }
    __syncthreads();

    const int row = tid >> 5;             // 0..15
    const int t4  = (tid & 31) * 4;       // 0,4,...,124
    float a[4] = {0.f, 0.f, 0.f, 0.f};

    #pragma unroll
    for (int u = 0; u < 5; u++) {
        const float* rp = &Ts[(row + u) * 132 + t4];
        float4 xa = *(const float4*)rp;
        float4 xc = *(const float4*)(rp + 4);
        float xv[8] = {xa.x, xa.y, xa.z, xa.w, xc.x, xc.y, xc.z, xc.w};
        #pragma unroll
        for (int v = 0; v < 5; v++) {
            float dv = sd[u * 5 + v];
            #pragma unroll
            for (int j = 0; j < 4; j++) a[j] = fmaf(dv, xv[v + j], a[j]);
        }
    }
    float4 o = make_float4(a[0], a[1], a[2], a[3]);
    *(float4*)&out[(size_t)bc * HW + (y0 + row) * W_ + t4] = o;
}

// ---------------- launch ----------------
extern "C" void kernel_launch(void* const* d_in, const int* in_sizes, int n_in,
                              void* d_out, int out_size) {
    const float* x = (const float*)d_in[0];
    const float* w = (const float*)d_in[1];
    float* out = (float*)d_out;

    static bool attr_set = false;
    if (!attr_set) {
        cudaFuncSetAttribute(main_conv_kernel,
                             cudaFuncAttributeMaxDynamicSharedMemorySize,
                             SMEM_FLOATS * sizeof(float));
        attr_set = true;
    }

    prep_kernel<<<7, 256>>>(w);
    main_conv_kernel<<<dim3(128, 16), 256, SMEM_FLOATS * sizeof(float)>>>(x);
    dog_kernel<<<dim3(1024, 8), 512>>>(out);
}

// round 5
// speedup vs baseline: 3.7755x; 3.7755x over previous
#include <cuda_runtime.h>
#include <cuda_fp16.h>
#include <cstdint>
#include <math.h>

// Problem constants
#define B_   16
#define CIN  64
#define COUT 64
#define H_   128
#define W_   128
#define HW   (H_*W_)          // 16384
#define NPIX (B_*COUT*HW)     // 16,777,216

#define XPAD 72               // fp16 per padded-X row (144 B, 16B-aligned rows)
#define WPAD 72               // fp16 per W row (144 B) -> B-frag LDS conflict-free

// ---------------- device scratch (static, no allocation) ----------------
__device__ __align__(16) __half g_wh[25 * 64 * WPAD];   // [kh*5+kw][cout][WPAD]
__device__ float g_dog[25];
__device__ __align__(16) float g_ybuf[NPIX];

__device__ __forceinline__ int refl(int i) {
    if (i < 0) return -i;
    if (i > 127) return 254 - i;
    return i;
}

__device__ __forceinline__ uint32_t smem_u32(const void* p) {
    uint32_t a;
    asm("{ .reg .u64 t; cvta.to.shared.u64 t, %1; cvt.u32.u64 %0, t; }"
        : "=r"(a) : "l"(p));
    return a;
}

// ---------------- kernel 1: weight prep ----------------
__global__ void prep_kernel(const float* __restrict__ w) {
    int t = blockIdx.x * blockDim.x + threadIdx.x;
    if (t < 1600) {
        int o = t / 25, khw = t % 25;
        float s = 0.f;
        #pragma unroll 8
        for (int ci = 0; ci < CIN; ci++) {
            float v = w[o * 1600 + ci * 25 + khw];
            s += v * v;
        }
        float inv = 1.f / fmaxf(sqrtf(s), 1e-12f);
        __half* dst = g_wh + (size_t)(khw * 64 + o) * WPAD;
        #pragma unroll 8
        for (int ci = 0; ci < CIN; ci++) {
            float wn = fabsf(w[o * 1600 + ci * 25 + khw]) * inv;
            dst[ci] = __float2half(wn);
        }
        for (int ci = CIN; ci < WPAD; ci++) dst[ci] = __float2half(0.f);
    }
    if (t < 25) {
        int u = t / 5 - 2, v = t % 5 - 2;
        float d2 = (float)(u * u + v * v);
        const float two_pi = 6.2831853071795864769f;
        const float ae = 1.f / (two_pi * 1.44f);   // sigma_e = 1.2
        const float ai = 1.f / (two_pi * 1.96f);   // sigma_i = 1.4
        float val = ae * expf(-d2 / (2.f * 1.44f)) - ai * expf(-d2 / (2.f * 1.96f));
        g_dog[t] = val / (ae - ai);
    }
}

// ---------------- kernel 2: fp16 HMMA implicit-GEMM conv + cosine ----------------
// Grid (64, 16): CTA = 2 output y-rows x 128 px x 64 cout of batch b. 256 thr = 8 warps.
// Warp w: yrow = w>>2, px block = (w&3)*32. Acc in registers across all 25 taps.
// smem: Ws[5][64][WPAD] fp16 (46080) | Xs[2][132][XPAD] fp16 (38016) | Ssum[2*132] f32 (1056)
#define WS_BYTES (5 * 64 * WPAD * 2)          // 46080
#define XS_BYTES (2 * 132 * XPAD * 2)         // 38016
#define DSMEM    (WS_BYTES + XS_BYTES + 264 * 4)  // 85152

__global__ __launch_bounds__(256, 2)
void main_mma_kernel(const float* __restrict__ x) {
    extern __shared__ char dsm[];
    __half* Ws   = (__half*)dsm;
    __half* Xs   = (__half*)(dsm + WS_BYTES);
    float*  Ssum = (float*)(dsm + WS_BYTES + XS_BYTES);

    const int tid  = threadIdx.x;
    const int warp = tid >> 5;
    const int lane = tid & 31;
    const int r    = warp >> 2;           // yrow 0..1
    const int px0  = (warp & 3) * 32;     // pixel block
    const int b    = blockIdx.y;
    const int y0   = blockIdx.x * 2;

    // ldmatrix per-lane row mapping
    const int m_off = ((lane >> 3) & 1) * 8 + (lane & 7);
    const int k_off = (lane >> 4) * 8;

    float acc[2][8][4];
    #pragma unroll
    for (int mt = 0; mt < 2; mt++)
        #pragma unroll
        for (int nt = 0; nt < 8; nt++)
            #pragma unroll
            for (int i = 0; i < 4; i++) acc[mt][nt][i] = 0.f;

    for (int kh = 0; kh < 5; kh++) {
        __syncthreads();   // everyone done reading previous kh's smem

        // ---- copy W tiles for this kh (46080 B) ----
        {
            const uint4* src = (const uint4*)(g_wh + (size_t)kh * 5 * 64 * WPAD);
            uint4* dst = (uint4*)Ws;
            for (int i = tid; i < 2880; i += 256) dst[i] = src[i];
        }

        // ---- stage X: 2 rows x 64 ci x 132 padded px, transpose to [px][ci] fp16 ----
        for (int it = 0; it < 16; it++) {
            int pair = warp + (it << 3);          // 0..127
            int rr = pair >> 6, ci = pair & 63;
            int ry = refl(y0 + rr + kh - 2);
            const float* gp = x + ((size_t)b * CIN + ci) * HW + (size_t)ry * W_;
            float4 v = ((const float4*)gp)[lane];
            __half* xrow = Xs + (size_t)(rr * 132) * XPAD + ci;
            int p = lane * 4 + 2;
            xrow[(size_t)(p + 0) * XPAD] = __float2half(v.x);
            xrow[(size_t)(p + 1) * XPAD] = __float2half(v.y);
            xrow[(size_t)(p + 2) * XPAD] = __float2half(v.z);
            xrow[(size_t)(p + 3) * XPAD] = __float2half(v.w);
            if (lane < 4) {
                const int ppx_e[4] = {0, 1, 130, 131};
                const int src_c[4] = {2, 1, 126, 125};
                xrow[(size_t)ppx_e[lane] * XPAD] = __float2half(gp[src_c[lane]]);
            }
        }
        __syncthreads();

        // ---- per-column sum of x^2 over ALL 64 ci (8 x uint4 = 64 halves) ----
        for (int c = tid; c < 264; c += 256) {
            const uint4* col = (const uint4*)(Xs + (size_t)c * XPAD);
            float s = 0.f;
            #pragma unroll
            for (int i = 0; i < 8; i++) {
                uint4 u = col[i];
                const uint32_t uu[4] = {u.x, u.y, u.z, u.w};
                #pragma unroll
                for (int j = 0; j < 4; j++) {
                    __half2 h = *(const __half2*)&uu[j];
                    float2 f = __half22float2(h);
                    s = fmaf(f.x, f.x, fmaf(f.y, f.y, s));
                }
            }
            Ssum[c] = (kh == 0 ? 0.f : Ssum[c]) + s;
        }

        // ---- 5 taps: GEMM M=32 x N=64 x K=64 per warp, acc persists ----
        #pragma unroll
        for (int kw = 0; kw < 5; kw++) {
            const __half* Ab = Xs + (size_t)(r * 132 + px0 + kw) * XPAD;
            #pragma unroll
            for (int kt = 0; kt < 4; kt++) {
                const int k0 = kt * 16;
                uint32_t a[2][4];
                #pragma unroll
                for (int mt = 0; mt < 2; mt++) {
                    uint32_t ad = smem_u32(Ab + (size_t)(mt * 16 + m_off) * XPAD + k0 + k_off);
                    asm volatile(
                        "ldmatrix.sync.aligned.m8n8.x4.shared.b16 {%0,%1,%2,%3}, [%4];"
                        : "=r"(a[mt][0]), "=r"(a[mt][1]), "=r"(a[mt][2]), "=r"(a[mt][3])
                        : "r"(ad));
                }
                const __half* Bb = Ws + (size_t)(kw * 64) * WPAD + k0 + (lane & 3) * 2;
                #pragma unroll
                for (int nt = 0; nt < 8; nt++) {
                    const __half* bp = Bb + (size_t)(nt * 8 + (lane >> 2)) * WPAD;
                    uint32_t b0 = *(const uint32_t*)bp;
                    uint32_t b1 = *(const uint32_t*)(bp + 8);
                    #pragma unroll
                    for (int mt = 0; mt < 2; mt++) {
                        asm volatile(
                            "mma.sync.aligned.m16n8k16.row.col.f32.f16.f16.f32 "
                            "{%0,%1,%2,%3}, {%4,%5,%6,%7}, {%8,%9}, {%0,%1,%2,%3};"
                            : "+f"(acc[mt][nt][0]), "+f"(acc[mt][nt][1]),
                              "+f"(acc[mt][nt][2]), "+f"(acc[mt][nt][3])
                            : "r"(a[mt][0]), "r"(a[mt][1]), "r"(a[mt][2]), "r"(a[mt][3]),
                              "r"(b0), "r"(b1));
                    }
                }
            }
        }
    }
    __syncthreads();   // all taps done; smem free for epilogue reuse (Ssum region untouched)

    // ---- epilogue: cosine norm + transpose via smem + coalesced store ----
    float inv[2][2];
    #pragma unroll
    for (int mt = 0; mt < 2; mt++)
        #pragma unroll
        for (int h = 0; h < 2; h++) {
            int p = px0 + mt * 16 + (lane >> 2) + h * 8;   // output px (0..127)
            const float* sp = Ssum + r * 132 + p;           // window p..p+4
            float s = sp[0] + sp[1] + sp[2] + sp[3] + sp[4];
            inv[mt][h] = rsqrtf(s + 1e-8f);
        }

    float* buf = (float*)dsm + warp * (64 * 36);   // [64 cout][36] per warp (73728 B < Ssum off)
    #pragma unroll
    for (int mt = 0; mt < 2; mt++)
        #pragma unroll
        for (int nt = 0; nt < 8; nt++)
            #pragma unroll
            for (int reg = 0; reg < 4; reg++) {
                int co  = nt * 8 + (lane & 3) * 2 + (reg & 1);
                int pxl = mt * 16 + (lane >> 2) + (reg >> 1) * 8;
                buf[co * 36 + pxl] = acc[mt][nt][reg] * inv[mt][reg >> 1];
            }
    __syncwarp();

    const int y = y0 + r;
    #pragma unroll
    for (int it = 0; it < 16; it++) {
        int row = it * 4 + (lane >> 3);   // cout
        int seg = lane & 7;               // 4-px segment
        float4 v = *(const float4*)&buf[row * 36 + seg * 4];
        *(float4*)&g_ybuf[(((size_t)b * COUT + row) * H_ + y) * W_ + px0 + seg * 4] = v;
    }
}

// ---------------- kernel 3: depthwise 5x5 DoG (zero pad) ----------------
__global__ __launch_bounds__(512)
void dog_kernel(float* __restrict__ out) {
    __shared__ float Ts[20 * 132];
    __shared__ float sd[25];

    const int tid = threadIdx.x;
    const int bc  = blockIdx.x;
    const int y0  = blockIdx.y * 16;

    if (tid < 25) sd[tid] = g_dog[tid];

    const float* src = g_ybuf + (size_t)bc * HW;
    for (int idx = tid; idx < 20 * 132; idx += 512) {
        int rr = idx / 132;
        int c  = idx - rr * 132;
        int gy = y0 + rr - 2;
        int gx = c - 2;
        float v = 0.f;
        if (gy >= 0 && gy < H_ && gx >= 0 && gx < W_) v = src[gy * W_ + gx];
        Ts[idx] = v;
    }
    __syncthreads();

    const int row = tid >> 5;
    const int t4  = (tid & 31) * 4;
    float a[4] = {0.f, 0.f, 0.f, 0.f};

    #pragma unroll
    for (int u = 0; u < 5; u++) {
        const float* rp = &Ts[(row + u) * 132 + t4];
        float4 xa = *(const float4*)rp;
        float4 xc = *(const float4*)(rp + 4);
        float xv[8] = {xa.x, xa.y, xa.z, xa.w, xc.x, xc.y, xc.z, xc.w};
        #pragma unroll
        for (int v = 0; v < 5; v++) {
            float dv = sd[u * 5 + v];
            #pragma unroll
            for (int j = 0; j < 4; j++) a[j] = fmaf(dv, xv[v + j], a[j]);
        }
    }
    float4 o = make_float4(a[0], a[1], a[2], a[3]);
    *(float4*)&out[(size_t)bc * HW + (y0 + row) * W_ + t4] = o;
}

// ---------------- launch ----------------
extern "C" void kernel_launch(void* const* d_in, const int* in_sizes, int n_in,
                              void* d_out, int out_size) {
    const float* x = (const float*)d_in[0];
    const float* w = (const float*)d_in[1];
    float* out = (float*)d_out;

    static bool attr_set = false;
    if (!attr_set) {
        cudaFuncSetAttribute(main_mma_kernel,
                             cudaFuncAttributeMaxDynamicSharedMemorySize, DSMEM);
        attr_set = true;
    }

    prep_kernel<<<7, 256>>>(w);
    main_mma_kernel<<<dim3(64, 16), 256, DSMEM>>>(x);
    dog_kernel<<<dim3(1024, 8), 512>>>(out);
}

// round 6
// speedup vs baseline: 5.1170x; 1.3553x over previous
#include <cuda_runtime.h>
#include <cuda_fp16.h>
#include <cstdint>
#include <math.h>

// Problem constants
#define B_   16
#define CIN  64
#define COUT 64
#define H_   128
#define W_   128
#define HW   (H_*W_)          // 16384
#define NPIX (B_*COUT*HW)     // 16,777,216

#define XPAD 72               // halves per px row (144 B): ldmatrix rows 16B-aligned
#define WPAD 72
#define XROW (132 * XPAD)     // halves per staged input row

// ---------------- device scratch (static, no allocation) ----------------
__device__ __align__(16) __half g_wh[25 * 64 * WPAD];   // [khw][cout][WPAD]
__device__ float g_dog[25];
__device__ __align__(16) float g_ybuf[NPIX];

__device__ __forceinline__ int refl(int i) {
    if (i < 0) return -i;
    if (i > 127) return 254 - i;
    return i;
}

__device__ __forceinline__ uint32_t smem_u32(const void* p) {
    uint32_t a;
    asm("{ .reg .u64 t; cvta.to.shared.u64 t, %1; cvt.u32.u64 %0, t; }"
        : "=r"(a) : "l"(p));
    return a;
}

// ---------------- kernel 1: weight prep (one block per cout) ----------------
__global__ __launch_bounds__(128)
void prep_kernel(const float* __restrict__ w) {
    __shared__ float ws[1600];
    __shared__ float invn[25];
    const int tid = threadIdx.x;
    const int o = blockIdx.x;

    for (int i = tid; i < 1600; i += 128) ws[i] = w[o * 1600 + i];
    __syncthreads();
    if (tid < 25) {
        float s = 0.f;
        #pragma unroll 8
        for (int ci = 0; ci < CIN; ci++) {
            float v = ws[ci * 25 + tid];
            s += v * v;
        }
        invn[tid] = 1.f / fmaxf(sqrtf(s), 1e-12f);
    }
    __syncthreads();
    for (int i = tid; i < 1600; i += 128) {
        int khw = i >> 6, ci = i & 63;
        float v = fabsf(ws[ci * 25 + khw]) * invn[khw];
        g_wh[(size_t)(khw * 64 + o) * WPAD + ci] = __float2half(v);
    }
    if (o == 0 && tid < 25) {
        int u = tid / 5 - 2, v = tid % 5 - 2;
        float d2 = (float)(u * u + v * v);
        const float two_pi = 6.2831853071795864769f;
        const float ae = 1.f / (two_pi * 1.44f);   // sigma_e = 1.2
        const float ai = 1.f / (two_pi * 1.96f);   // sigma_i = 1.4
        float val = ae * expf(-d2 / (2.f * 1.44f)) - ai * expf(-d2 / (2.f * 1.96f));
        g_dog[tid] = val / (ae - ai);
    }
}

// ---------------- kernel 2: fp16 HMMA implicit-GEMM conv + cosine ----------------
// Grid (32, 16): CTA = 4 output y-rows x 128 px x 64 cout. 512 thr = 16 warps.
// Warp w: yrow g = w>>2, px block (w&3)*32. X staged ONCE (8 input rows).
// smem: Ws[5kw][64][WPAD] 46080 | Xs[8 rows][132 px][XPAD] 152064 | Crow[8*132] | Ssum[4*132]
#define WS_BYTES (5 * 64 * WPAD * 2)            // 46080
#define XS_BYTES (8 * 132 * XPAD * 2)           // 152064
#define CROW_FLOATS (8 * 132)
#define SSUM_FLOATS (4 * 132)
#define DSMEM (WS_BYTES + XS_BYTES + (CROW_FLOATS + SSUM_FLOATS) * 4)  // 204480

__global__ __launch_bounds__(512, 1)
void main_mma_kernel(const float* __restrict__ x) {
    extern __shared__ char dsm[];
    __half* Ws   = (__half*)dsm;
    __half* Xs   = (__half*)(dsm + WS_BYTES);
    float*  Crow = (float*)(dsm + WS_BYTES + XS_BYTES);
    float*  Ssum = Crow + CROW_FLOATS;

    const int tid  = threadIdx.x;
    const int warp = tid >> 5;
    const int lane = tid & 31;
    const int g    = warp >> 2;           // output yrow 0..3
    const int px0  = (warp & 3) * 32;     // pixel block
    const int b    = blockIdx.y;
    const int y0   = blockIdx.x * 4;

    // ---- stage X once: 8 input rows, transpose [ci][px] -> [px][ci] ----
    // task = (staged row s, ci quad q). lane -> px stride 1 (coalesced LDG, 4-way STS).
    for (int task = warp; task < 128; task += 16) {
        int s = task >> 4, q = task & 15;
        int gy = refl(y0 + s - 2);
        const float* base = x + ((size_t)b * CIN + q * 4) * HW + (size_t)gy * W_;
        #pragma unroll
        for (int k = 0; k < 5; k++) {
            int c = lane + 32 * k;
            if (c < 132) {
                int gc = refl(c - 2);
                float v0 = base[0 * HW + gc];
                float v1 = base[1 * HW + gc];
                float v2 = base[2 * HW + gc];
                float v3 = base[3 * HW + gc];
                uint32_t p0, p1;
                asm("cvt.rn.f16x2.f32 %0, %1, %2;" : "=r"(p0) : "f"(v1), "f"(v0));
                asm("cvt.rn.f16x2.f32 %0, %1, %2;" : "=r"(p1) : "f"(v3), "f"(v2));
                *(uint2*)(Xs + (size_t)s * XROW + (size_t)c * XPAD + q * 4) =
                    make_uint2(p0, p1);
            }
        }
    }
    __syncthreads();

    // ---- per staged-row column sums of x^2 ----
    for (int t = tid; t < 1056; t += 512) {
        int s = t / 132, c = t - s * 132;
        const uint4* p = (const uint4*)(Xs + (size_t)s * XROW + (size_t)c * XPAD);
        float sacc = 0.f;
        #pragma unroll
        for (int i = 0; i < 8; i++) {
            uint4 u = p[i];
            const uint32_t uu[4] = {u.x, u.y, u.z, u.w};
            #pragma unroll
            for (int j = 0; j < 4; j++) {
                float2 f = __half22float2(*(const __half2*)&uu[j]);
                sacc = fmaf(f.x, f.x, fmaf(f.y, f.y, sacc));
            }
        }
        Crow[t] = sacc;
    }
    __syncthreads();

    // ---- 5-row window sums -> Ssum[out row][padded col] ----
    for (int t = tid; t < 528; t += 512) {
        int r = t / 132, c = t - r * 132;
        Ssum[t] = Crow[(r + 0) * 132 + c] + Crow[(r + 1) * 132 + c]
                + Crow[(r + 2) * 132 + c] + Crow[(r + 3) * 132 + c]
                + Crow[(r + 4) * 132 + c];
    }

    // ---- accumulators ----
    float acc[2][8][4];
    #pragma unroll
    for (int mt = 0; mt < 2; mt++)
        #pragma unroll
        for (int nt = 0; nt < 8; nt++)
            #pragma unroll
            for (int i = 0; i < 4; i++) acc[mt][nt][i] = 0.f;

    // ldmatrix lane mappings
    const int m_off = ((lane >> 3) & 1) * 8 + (lane & 7);      // A rows
    const int k_off = (lane >> 4) * 8;                          // A k segment
    const int brow  = (lane & 7) + ((lane >> 4) << 3);          // B n row
    const int bk    = ((lane >> 3) & 1) * 8;                    // B k segment

    for (int kh = 0; kh < 5; kh++) {
        __syncthreads();   // previous kh's taps done reading Ws
        {
            const uint4* src = (const uint4*)(g_wh + (size_t)kh * 5 * 64 * WPAD);
            uint4* dst = (uint4*)Ws;
            for (int i = tid; i < 2880; i += 512) dst[i] = src[i];
        }
        __syncthreads();

        #pragma unroll
        for (int kw = 0; kw < 5; kw++) {
            const __half* Ab = Xs + (size_t)(g + kh) * XROW
                                  + (size_t)(px0 + kw) * XPAD;
            // A fragments for all 4 k-chunks
            uint32_t a[4][2][4];
            #pragma unroll
            for (int kt = 0; kt < 4; kt++)
                #pragma unroll
                for (int mt = 0; mt < 2; mt++) {
                    uint32_t ad = smem_u32(Ab + (size_t)(mt * 16 + m_off) * XPAD
                                              + kt * 16 + k_off);
                    asm volatile(
                        "ldmatrix.sync.aligned.m8n8.x4.shared.b16 {%0,%1,%2,%3}, [%4];"
                        : "=r"(a[kt][mt][0]), "=r"(a[kt][mt][1]),
                          "=r"(a[kt][mt][2]), "=r"(a[kt][mt][3])
                        : "r"(ad));
                }
            // B via ldmatrix.x4: regs = {b0,b1 of nt even; b0,b1 of nt odd}
            #pragma unroll
            for (int np = 0; np < 4; np++) {
                #pragma unroll
                for (int kt = 0; kt < 4; kt++) {
                    uint32_t bb[4];
                    uint32_t bd = smem_u32(Ws + (size_t)(kw * 64 + np * 16 + brow) * WPAD
                                              + kt * 16 + bk);
                    asm volatile(
                        "ldmatrix.sync.aligned.m8n8.x4.shared.b16 {%0,%1,%2,%3}, [%4];"
                        : "=r"(bb[0]), "=r"(bb[1]), "=r"(bb[2]), "=r"(bb[3])
                        : "r"(bd));
                    #pragma unroll
                    for (int mt = 0; mt < 2; mt++) {
                        asm volatile(
                            "mma.sync.aligned.m16n8k16.row.col.f32.f16.f16.f32 "
                            "{%0,%1,%2,%3}, {%4,%5,%6,%7}, {%8,%9}, {%0,%1,%2,%3};"
                            : "+f"(acc[mt][2 * np][0]), "+f"(acc[mt][2 * np][1]),
                              "+f"(acc[mt][2 * np][2]), "+f"(acc[mt][2 * np][3])
                            : "r"(a[kt][mt][0]), "r"(a[kt][mt][1]),
                              "r"(a[kt][mt][2]), "r"(a[kt][mt][3]),
                              "r"(bb[0]), "r"(bb[1]));
                        asm volatile(
                            "mma.sync.aligned.m16n8k16.row.col.f32.f16.f16.f32 "
                            "{%0,%1,%2,%3}, {%4,%5,%6,%7}, {%8,%9}, {%0,%1,%2,%3};"
                            : "+f"(acc[mt][2 * np + 1][0]), "+f"(acc[mt][2 * np + 1][1]),
                              "+f"(acc[mt][2 * np + 1][2]), "+f"(acc[mt][2 * np + 1][3])
                            : "r"(a[kt][mt][0]), "r"(a[kt][mt][1]),
                              "r"(a[kt][mt][2]), "r"(a[kt][mt][3]),
                              "r"(bb[2]), "r"(bb[3]));
                    }
                }
            }
        }
    }
    __syncthreads();   // all taps done; Xs region reusable for epilogue

    // ---- epilogue: cosine norm + smem transpose + coalesced store ----
    float inv[2][2];
    #pragma unroll
    for (int mt = 0; mt < 2; mt++)
        #pragma unroll
        for (int h = 0; h < 2; h++) {
            int p = px0 + mt * 16 + (lane >> 2) + h * 8;
            const float* sp = Ssum + g * 132 + p;
            float s = sp[0] + sp[1] + sp[2] + sp[3] + sp[4];
            inv[mt][h] = rsqrtf(s + 1e-8f);
        }

    float* buf = (float*)(dsm + WS_BYTES) + warp * (64 * 36);
    #pragma unroll
    for (int mt = 0; mt < 2; mt++)
        #pragma unroll
        for (int nt = 0; nt < 8; nt++)
            #pragma unroll
            for (int reg = 0; reg < 4; reg++) {
                int co  = nt * 8 + (lane & 3) * 2 + (reg & 1);
                int pxl = mt * 16 + (lane >> 2) + (reg >> 1) * 8;
                buf[co * 36 + pxl] = acc[mt][nt][reg] * inv[mt][reg >> 1];
            }
    __syncwarp();

    const int y = y0 + g;
    #pragma unroll
    for (int it = 0; it < 16; it++) {
        int row = it * 4 + (lane >> 3);   // cout
        int seg = lane & 7;               // 4-px segment
        float4 v = *(const float4*)&buf[row * 36 + seg * 4];
        *(float4*)&g_ybuf[(((size_t)b * COUT + row) * H_ + y) * W_ + px0 + seg * 4] = v;
    }
}

// ---------------- kernel 3: depthwise 5x5 DoG (zero pad) ----------------
__global__ __launch_bounds__(512)
void dog_kernel(float* __restrict__ out) {
    __shared__ float Ts[20 * 132];
    __shared__ float sd[25];

    const int tid = threadIdx.x;
    const int bc  = blockIdx.x;
    const int y0  = blockIdx.y * 16;

    if (tid < 25) sd[tid] = g_dog[tid];

    const float* src = g_ybuf + (size_t)bc * HW;
    for (int idx = tid; idx < 20 * 132; idx += 512) {
        int rr = idx / 132;
        int c  = idx - rr * 132;
        int gy = y0 + rr - 2;
        int gx = c - 2;
        float v = 0.f;
        if (gy >= 0 && gy < H_ && gx >= 0 && gx < W_) v = src[gy * W_ + gx];
        Ts[idx] = v;
    }
    __syncthreads();

    const int row = tid >> 5;
    const int t4  = (tid & 31) * 4;
    float a[4] = {0.f, 0.f, 0.f, 0.f};

    #pragma unroll
    for (int u = 0; u < 5; u++) {
        const float* rp = &Ts[(row + u) * 132 + t4];
        float4 xa = *(const float4*)rp;
        float4 xc = *(const float4*)(rp + 4);
        float xv[8] = {xa.x, xa.y, xa.z, xa.w, xc.x, xc.y, xc.z, xc.w};
        #pragma unroll
        for (int v = 0; v < 5; v++) {
            float dv = sd[u * 5 + v];
            #pragma unroll
            for (int j = 0; j < 4; j++) a[j] = fmaf(dv, xv[v + j], a[j]);
        }
    }
    float4 o = make_float4(a[0], a[1], a[2], a[3]);
    *(float4*)&out[(size_t)bc * HW + (y0 + row) * W_ + t4] = o;
}

// ---------------- launch ----------------
extern "C" void kernel_launch(void* const* d_in, const int* in_sizes, int n_in,
                              void* d_out, int out_size) {
    const float* x = (const float*)d_in[0];
    const float* w = (const float*)d_in[1];
    float* out = (float*)d_out;

    static bool attr_set = false;
    if (!attr_set) {
        cudaFuncSetAttribute(main_mma_kernel,
                             cudaFuncAttributeMaxDynamicSharedMemorySize, DSMEM);
        attr_set = true;
    }

    prep_kernel<<<64, 128>>>(w);
    main_mma_kernel<<<dim3(32, 16), 512, DSMEM>>>(x);
    dog_kernel<<<dim3(1024, 8), 512>>>(out);
}